// round 12
// baseline (speedup 1.0000x reference)
#include <cuda_runtime.h>
#include <cuda_bf16.h>
#include <cstdint>

// ---------------------------------------------------------------------------
// KAN 2-layer network on tcgen05 (kind::f16, bf16 inputs, fp32 accum) using a
// 3-term bf16 split for fp32-grade precision:
//   a*b ~= ah*bh + ah*bl + al*bh        (al*bl ~ 2^-18 dropped)
// f32x2 SIMT fallback for the non-arch-specific compute_103 pass.
//
// R11: 9-warp block. Warps 0-7 (256 thr) = A producers (2 features/thread,
// X prefetched ahead of the empty-wait); warp 8 = MMA issuer; warps 0-3 =
// TMEM epilogue. B tiles pre-split/pre-swizzled in gmem, fetched with one
// cp.async.bulk per tile onto the same barrier as the producer arrivals.
// ---------------------------------------------------------------------------

#if defined(__CUDA_ARCH__) && (defined(__CUDA_ARCH_FEAT_SM103_ALL) || \
                               defined(__CUDA_ARCH_FEAT_SM100_ALL) || \
                               defined(__CUDA_ARCH_FEAT_SM101_ALL))
#define KAN_TCGEN05 1
#else
#define KAN_TCGEN05 0
#endif

namespace {
constexpr int BATCH = 8192;
constexpr int F1 = 2513, N1 = 512;
constexpr int F2 = 512;
constexpr int N2 = 300;
constexpr int KT1 = 629;   // ceil(2513*8/32) k-tiles (32 expanded k each)
constexpr int KT2 = 128;   // 512*8/32
constexpr int NT1 = 4;
constexpr int NT2 = 3;
constexpr int NSTAGE = 3;
constexpr int TILE_BYTES = 16384;   // 128 rows x 128B
constexpr int TILE_U32 = 4096;
constexpr int NTHREADS = 288;       // 8 producer warps + 1 MMA warp

constexpr int OFF_TMEM = 0;
constexpr int OFF_BAR = 16;
constexpr int OFF_TILES = 1024;
constexpr int STAGE_BYTES = 32768;  // A(16KB) + B(16KB)
constexpr int SMEM_TOTAL = OFF_TILES + NSTAGE * STAGE_BYTES;  // 99328
}  // namespace

__device__ uint32_t g_w1t[(size_t)NT1 * KT1 * TILE_U32];
__device__ uint32_t g_w2t[(size_t)NT2 * KT2 * TILE_U32];
__device__ float g_h[(size_t)BATCH * 512];

typedef unsigned long long u64;

// --------------------- closed-form cubic B-spline expansion ----------------
// grid g[k] = (k-3)*0.4 - 1; inputs >= 0. t = floor(x*2.5 + 5.5); nonzero
// bases j in [t-3,t] ∩ [2,7].  o[0]=silu(x), o[1..6]=B_{2..7}(x), o[7]=0.
__device__ __forceinline__ void feats8(float x, float* o) {
    float s = fmaf(x, 2.5f, 5.5f);
    float tf = floorf(s);
    int t = (int)tf;
    float u = s - tf;
    float u2 = u * u, u3 = u2 * u;
    float p0 = u3 * (1.f / 6.f);
    float p1 = (fmaf(-3.f, u3, 3.f * u2) + 3.f * u + 1.f) * (1.f / 6.f);
    float p2 = (fmaf(3.f, u3, -6.f * u2) + 4.f) * (1.f / 6.f);
    float w = 1.f - u;
    float p3 = w * w * w * (1.f / 6.f);
    o[0] = x * __fdividef(1.f, 1.f + __expf(-x));
#pragma unroll
    for (int j = 2; j <= 7; j++) {
        int d = t - j;
        float v = 0.f;
        if (d == 0) v = p0;
        else if (d == 1) v = p1;
        else if (d == 2) v = p2;
        else if (d == 3) v = p3;
        o[j - 1] = v;
    }
    o[7] = 0.f;
}

__device__ __forceinline__ float bf_lo_f(uint32_t u) {
    return __uint_as_float(u << 16);
}
__device__ __forceinline__ float bf_hi_f(uint32_t u) {
    return __uint_as_float(u & 0xffff0000u);
}
__device__ __forceinline__ uint32_t pack_bf2(float a, float b) {
    __nv_bfloat162 p = __floats2bfloat162_rn(a, b);  // a->low, b->high
    return *reinterpret_cast<uint32_t*>(&p);
}

// --------------------------- weight prep -----------------------------------
// Tile T = ntile*KT + kt: 128 rows x 8 chunks of 16B, stored chunk =
// logical ^ (row&7).  Logical chunk j: j<4 -> hi bf16 of feature f=kt*4+j,
// slots s=0..7;  j>=4 -> lo residual of feature f=kt*4+(j-4).
// slot s: 0 -> base_w[n][f]; 1..6 -> spline_w[n][f][s+1]*scaler; 7 -> 0.
__global__ void prep_kernel(uint32_t* __restrict__ dst,
                            const float* __restrict__ base_w,
                            const float* __restrict__ spline_w,
                            const float* __restrict__ scaler, int KT, int F,
                            int Nsrc, int totalChunks) {
    int idx = blockIdx.x * blockDim.x + threadIdx.x;
    if (idx >= totalChunks) return;
    int cw = idx & 1023;
    int T = idx >> 10;
    int ntile = T / KT;
    int kt = T - ntile * KT;
    int r = cw >> 3;
    int js = cw & 7;
    int j = js ^ (r & 7);
    int c = j & 3;
    int isLo = j >> 2;
    int n = ntile * 128 + r;
    int f = kt * 4 + c;

    float wv[8];
#pragma unroll
    for (int s = 0; s < 8; s++) {
        float val = 0.f;
        if (n < Nsrc && f < F && s < 7) {
            size_t src = (size_t)n * F + f;
            if (s == 0) val = base_w[src];
            else val = spline_w[src * 8 + s + 1] * scaler[src];
        }
        wv[s] = val;
    }
    uint32_t out[4];
#pragma unroll
    for (int w = 0; w < 4; w++) {
        uint32_t hu = pack_bf2(wv[2 * w], wv[2 * w + 1]);
        if (!isLo) {
            out[w] = hu;
        } else {
            float r0 = wv[2 * w] - bf_lo_f(hu);
            float r1 = wv[2 * w + 1] - bf_hi_f(hu);
            out[w] = pack_bf2(r0, r1);
        }
    }
    *reinterpret_cast<uint4*>(dst + (size_t)T * TILE_U32 + cw * 4) =
        make_uint4(out[0], out[1], out[2], out[3]);
}

// ----------------------------- fused GEMM ----------------------------------
__global__ void __launch_bounds__(NTHREADS, 2) kan_mma_kernel(
    const float* __restrict__ X, const uint32_t* __restrict__ Wt,
    float* __restrict__ C, int F, int KT, int Nout, int Cstride, int doRelu) {
#if KAN_TCGEN05
    // ======================= tcgen05 bf16x3 path ============================
    extern __shared__ __align__(1024) char smem[];
    uint32_t sb;
    asm("{ .reg .u64 t; cvta.to.shared.u64 t, %1; cvt.u32.u64 %0, t; }"
        : "=r"(sb) : "l"(smem));
    const int tid = threadIdx.x;
    const int wid = tid >> 5;
    const int lane = tid & 31;
    const int m0 = blockIdx.y * 128;
    const int ntile = blockIdx.x;
    const int n0 = ntile * 128;
    const uint32_t bar = sb + OFF_BAR;
    // abfull[s]=bar+s*8 (257: 256 producers + expect_tx arrive)
    // empty[s]=bar+(NSTAGE+s)*8 (1: MMA commit)   done=bar+2*NSTAGE*8 (1)

#define MBAR_INIT(addr, cnt) \
    asm volatile("mbarrier.init.shared.b64 [%0], %1;" ::"r"(addr), "r"(cnt) : "memory")
#define MBAR_ARRIVE(addr) \
    asm volatile("mbarrier.arrive.shared.b64 _, [%0];" ::"r"(addr) : "memory")
#define MBAR_WAIT(addr, parity)                                                  \
    do {                                                                         \
        uint32_t _m = (addr), _p = (parity), _d;                                 \
        asm volatile(                                                            \
            "{\n\t.reg .pred p;\n\t"                                             \
            "mbarrier.try_wait.parity.acquire.cta.shared::cta.b64 p, [%1], %2;\n\t" \
            "selp.b32 %0, 1, 0, p;\n\t}"                                         \
            : "=r"(_d) : "r"(_m), "r"(_p) : "memory");                           \
        if (!_d) {                                                               \
            asm volatile(                                                        \
                "{\n\t.reg .pred P1;\n\t"                                        \
                "WL_%=:\n\t"                                                     \
                "mbarrier.try_wait.parity.acquire.cta.shared::cta.b64 P1, [%0], %1, 0x989680;\n\t" \
                "@P1 bra.uni WD_%=;\n\t"                                         \
                "bra.uni WL_%=;\n\t"                                             \
                "WD_%=:\n\t}" ::"r"(_m), "r"(_p) : "memory");                    \
        }                                                                        \
    } while (0)
#define STS128X(a, r0, r1, r2, r3) \
    asm volatile("st.shared.v4.b32 [%0], {%1,%2,%3,%4};" ::"r"(a), "r"(r0), "r"(r1), "r"(r2), "r"(r3) : "memory")

    if (wid == 8) {
        asm volatile(
            "tcgen05.alloc.cta_group::1.sync.aligned.shared::cta.b32 [%0], %1;"
            ::"r"(sb + OFF_TMEM), "r"(128) : "memory");
        asm volatile("tcgen05.relinquish_alloc_permit.cta_group::1.sync.aligned;");
    }
    if (tid == 0) {
#pragma unroll
        for (int s = 0; s < NSTAGE; s++) {
            MBAR_INIT(bar + s * 8, 257);                 // abfull
            MBAR_INIT(bar + (NSTAGE + s) * 8, 1);        // empty
        }
        MBAR_INIT(bar + 2 * NSTAGE * 8, 1);              // done
    }
    __syncthreads();

    if (tid < 256) {
        // -------- producers: 2 features/thread, X prefetch, B bulk-copy -----
        const int row = tid & 127;
        const int half = tid >> 7;             // feature pair within the 4
        const int r7 = row & 7;
        const float* Xr = X + (size_t)(m0 + row) * F + 2 * half;
        const uint32_t rowb_base = sb + OFF_TILES + row * 128;

        float xc0, xc1, xn0, xn1;
        {
            int f = 2 * half;
            xc0 = (f < F) ? __ldg(Xr) : 0.f;
            xc1 = (f + 1 < F) ? __ldg(Xr + 1) : 0.f;
        }
        int stage = 0, ph = 1;
        for (int t = 0; t < KT; t++) {
            // prefetch next tile's X before blocking on empty
            if (t + 1 < KT) {
                int f = (t + 1) * 4 + 2 * half;
                xn0 = (f < F) ? __ldg(Xr + (t + 1) * 4) : 0.f;
                xn1 = (f + 1 < F) ? __ldg(Xr + (t + 1) * 4 + 1) : 0.f;
            } else {
                xn0 = xn1 = 0.f;
            }
            MBAR_WAIT(bar + (NSTAGE + stage) * 8, ph);
            uint32_t As = sb + OFF_TILES + stage * STAGE_BYTES;
            if (tid == 0) {
                uint32_t abfull = bar + stage * 8;
                asm volatile(
                    "mbarrier.arrive.expect_tx.shared.b64 _, [%0], %1;"
                    ::"r"(abfull), "r"(TILE_BYTES) : "memory");
                const char* src = (const char*)Wt +
                                  (size_t)(ntile * KT + t) * TILE_BYTES;
                asm volatile(
                    "cp.async.bulk.shared::cluster.global.mbarrier::complete_tx::bytes "
                    "[%0], [%1], %2, [%3];"
                    ::"r"(As + TILE_BYTES), "l"(src), "r"(TILE_BYTES),
                      "r"(abfull) : "memory");
            }
            uint32_t rowb = rowb_base + stage * STAGE_BYTES;
#pragma unroll
            for (int q = 0; q < 2; q++) {
                float x = q ? xc1 : xc0;
                float o[8];
                feats8(x, o);
                uint32_t hi[4], lo[4];
#pragma unroll
                for (int w = 0; w < 4; w++) {
                    uint32_t hu = pack_bf2(o[2 * w], o[2 * w + 1]);
                    float r0 = o[2 * w] - bf_lo_f(hu);
                    float r1 = o[2 * w + 1] - bf_hi_f(hu);
                    hi[w] = hu;
                    lo[w] = pack_bf2(r0, r1);
                }
                int c = 2 * half + q;
                STS128X(rowb + ((c ^ r7) << 4), hi[0], hi[1], hi[2], hi[3]);
                STS128X(rowb + (((4 + c) ^ r7) << 4), lo[0], lo[1], lo[2], lo[3]);
            }
            asm volatile("fence.proxy.async.shared::cta;" ::: "memory");
            MBAR_ARRIVE(bar + stage * 8);
            xc0 = xn0;
            xc1 = xn1;
            if (++stage == NSTAGE) { stage = 0; ph ^= 1; }
        }
    } else {
        // ----------------------------- MMA warp (wid 8) ---------------------
        uint32_t tmem;
        asm volatile("ld.shared.b32 %0, [%1];" : "=r"(tmem) : "r"(sb + OFF_TMEM));
        const uint32_t idesc = (1u << 4) | (1u << 7) | (1u << 10) |
                               ((128u / 8u) << 17) | ((128u / 16u) << 24);
        uint32_t is_elected;
        asm volatile(
            "{\n\t.reg .pred p;\n\telect.sync _|p, 0xFFFFFFFF;\n\t"
            "selp.b32 %0, 1, 0, p;\n\t}" : "=r"(is_elected));
        int stage = 0, ph = 0;
        for (int t = 0; t < KT; t++) {
            MBAR_WAIT(bar + stage * 8, ph);  // abfull (A arrivals + B tx)
            if (is_elected) {
                uint32_t As = sb + OFF_TILES + stage * STAGE_BYTES;
                uint64_t base = (uint64_t(2) << 61) | (uint64_t(1) << 46) |
                                (uint64_t(64) << 32) | (uint64_t(1) << 16);
                uint64_t ad = base | ((uint64_t)(As >> 4) & 0x3FFF);
                uint64_t bd = base | ((uint64_t)((As + TILE_BYTES) >> 4) & 0x3FFF);
                // hi bytes [0,64): k0 at +0, k1 at +2; lo bytes [64,128): +4,+6
                const int aoff[6] = {0, 2, 0, 2, 4, 6};
                const int boff[6] = {0, 2, 4, 6, 0, 2};
#pragma unroll
                for (int s = 0; s < 6; s++) {
                    uint32_t en = !(t == 0 && s == 0);
                    asm volatile(
                        "{\n\t.reg .pred p;\n\tsetp.ne.u32 p, %5, 0;\n\t"
                        "tcgen05.mma.cta_group::1.kind::f16 [%0], %1, %2, %3, "
                        "{%4,%4,%4,%4}, p;\n\t}"
                        :: "r"(tmem), "l"(ad + aoff[s]), "l"(bd + boff[s]),
                           "r"(idesc), "r"(0u), "r"(en)
                        : "memory");
                }
                asm volatile(
                    "tcgen05.commit.cta_group::1.mbarrier::arrive::one.shared::cluster.b64 [%0];"
                    ::"r"(bar + (NSTAGE + stage) * 8) : "memory");
            }
            if (++stage == NSTAGE) { stage = 0; ph ^= 1; }
        }
        if (is_elected)
            asm volatile(
                "tcgen05.commit.cta_group::1.mbarrier::arrive::one.shared::cluster.b64 [%0];"
                ::"r"(bar + 2 * NSTAGE * 8) : "memory");
    }

    uint32_t tmem_all = 0;
    if (wid < 4 || wid == 8) {
        asm volatile("ld.shared.b32 %0, [%1];" : "=r"(tmem_all) : "r"(sb + OFF_TMEM));
    }
    if (wid < 4) {
        // ----------------------------- epilogue -----------------------------
        MBAR_WAIT(bar + 2 * NSTAGE * 8, 0);
        asm volatile("tcgen05.fence::after_thread_sync;" ::: "memory");
        const int wrow = (wid << 5) + lane;  // TMEM lane = M row
        const size_t m = (size_t)m0 + wrow;
        const bool fullTile = (n0 + 128 <= Nout);
#pragma unroll 1
        for (int ch = 0; ch < 4; ch++) {
            uint32_t r[32];
            asm volatile(
                "tcgen05.ld.sync.aligned.32x32b.x32.b32 "
                "{%0,%1,%2,%3,%4,%5,%6,%7,%8,%9,%10,%11,%12,%13,%14,%15,"
                "%16,%17,%18,%19,%20,%21,%22,%23,%24,%25,%26,%27,%28,%29,%30,%31}, [%32];"
                : "=r"(r[0]), "=r"(r[1]), "=r"(r[2]), "=r"(r[3]), "=r"(r[4]),
                  "=r"(r[5]), "=r"(r[6]), "=r"(r[7]), "=r"(r[8]), "=r"(r[9]),
                  "=r"(r[10]), "=r"(r[11]), "=r"(r[12]), "=r"(r[13]), "=r"(r[14]),
                  "=r"(r[15]), "=r"(r[16]), "=r"(r[17]), "=r"(r[18]), "=r"(r[19]),
                  "=r"(r[20]), "=r"(r[21]), "=r"(r[22]), "=r"(r[23]), "=r"(r[24]),
                  "=r"(r[25]), "=r"(r[26]), "=r"(r[27]), "=r"(r[28]), "=r"(r[29]),
                  "=r"(r[30]), "=r"(r[31])
                : "r"(tmem_all + ch * 32));
            asm volatile("tcgen05.wait::ld.sync.aligned;" ::: "memory");
            float vals[32];
#pragma unroll
            for (int c = 0; c < 32; c++) {
                float v = __uint_as_float(r[c]);
                vals[c] = doRelu ? fmaxf(v, 0.f) : v;
            }
            int nb = n0 + ch * 32;
            float* dst = C + m * Cstride + nb;
            if (fullTile) {
#pragma unroll
                for (int g = 0; g < 8; g++)
                    *(float4*)(dst + g * 4) = make_float4(
                        vals[g * 4], vals[g * 4 + 1], vals[g * 4 + 2], vals[g * 4 + 3]);
            } else {
#pragma unroll
                for (int c = 0; c < 32; c++)
                    if (nb + c < Nout) dst[c] = vals[c];
            }
        }
        asm volatile("tcgen05.fence::before_thread_sync;" ::: "memory");
    }

    __syncthreads();
    if (wid == 8)
        asm volatile("tcgen05.dealloc.cta_group::1.sync.aligned.b32 %0, %1;"
                     ::"r"(tmem_all), "r"(128));

#else
    // ====================== f32x2 SIMT fallback path ========================
    extern __shared__ __align__(1024) float fsm[];
    float* As = fsm;              // [32][132]
    float* Bs = fsm + 32 * 132;   // [32][128]
    const int tid = threadIdx.x;
    const int tx = tid & 15;
    const int ty = tid >> 4;
    const int m0 = blockIdx.y * 128;
    const int ntile = blockIdx.x;
    const int n0 = ntile * 128;

    u64 acc[8][4];
#pragma unroll
    for (int i = 0; i < 8; i++)
#pragma unroll
        for (int j = 0; j < 4; j++) acc[i][j] = 0ull;

    for (int t = 0; t < KT; t++) {
        __syncthreads();
        if (tid < 256) {
            // B tile: de-swizzle + hi/lo recombine into fp32 [k][n]
            for (int p = tid; p < 512; p += 256) {
                int r = p >> 2, c = p & 3;
                const uint4* tb =
                    (const uint4*)(Wt + (size_t)(ntile * KT + t) * TILE_U32 + r * 32);
                uint4 h4 = __ldg(&tb[c ^ (r & 7)]);
                uint4 l4 = __ldg(&tb[(4 + c) ^ (r & 7)]);
                uint32_t hw[4] = {h4.x, h4.y, h4.z, h4.w};
                uint32_t lw[4] = {l4.x, l4.y, l4.z, l4.w};
#pragma unroll
                for (int w = 0; w < 4; w++) {
                    Bs[(c * 8 + 2 * w) * 128 + r] = bf_lo_f(hw[w]) + bf_lo_f(lw[w]);
                    Bs[(c * 8 + 2 * w + 1) * 128 + r] = bf_hi_f(hw[w]) + bf_hi_f(lw[w]);
                }
            }
            // A tile: expand fp32
#pragma unroll
            for (int q = 0; q < 2; q++) {
                int p = tid + q * 256;
                int fi = p & 3;
                int mm = p >> 2;
                int f = t * 4 + fi;
                float x = (f < F) ? __ldg(&X[(size_t)(m0 + mm) * F + f]) : 0.f;
                float o[8];
                feats8(x, o);
#pragma unroll
                for (int s = 0; s < 8; s++) As[(fi * 8 + s) * 132 + mm] = o[s];
            }
        }
        __syncthreads();
        if (tid < 256) {
            const float* Ap = As + ty * 8;
            const float* Bp = Bs + tx * 8;
#pragma unroll
            for (int k = 0; k < 32; k++) {
                float4 a0 = *(const float4*)(Ap + k * 132);
                float4 a1 = *(const float4*)(Ap + k * 132 + 4);
                ulonglong2 b01 = *(const ulonglong2*)(Bp + k * 128);
                ulonglong2 b23 = *(const ulonglong2*)(Bp + k * 128 + 4);
                u64 bb[4] = {b01.x, b01.y, b23.x, b23.y};
                float av[8] = {a0.x, a0.y, a0.z, a0.w, a1.x, a1.y, a1.z, a1.w};
#pragma unroll
                for (int i = 0; i < 8; i++) {
                    u64 aa;
                    unsigned ui = __float_as_uint(av[i]);
                    asm("mov.b64 %0, {%1, %1};" : "=l"(aa) : "r"(ui));
#pragma unroll
                    for (int j = 0; j < 4; j++)
                        asm("fma.rn.f32x2 %0, %1, %2, %0;"
                            : "+l"(acc[i][j]) : "l"(aa), "l"(bb[j]));
                }
            }
        }
    }
    if (tid < 256) {
        const int colBase = n0 + tx * 8;
#pragma unroll
        for (int i = 0; i < 8; i++) {
            size_t row = m0 + ty * 8 + i;
            float o[8];
#pragma unroll
            for (int j = 0; j < 4; j++) {
                o[2 * j] = __uint_as_float((unsigned)(acc[i][j] & 0xffffffffull));
                o[2 * j + 1] = __uint_as_float((unsigned)(acc[i][j] >> 32));
            }
#pragma unroll
            for (int e = 0; e < 8; e++) {
                float v = doRelu ? fmaxf(o[e], 0.f) : o[e];
                if (colBase + e < Nout) C[row * Cstride + colBase + e] = v;
            }
        }
    }
#endif
}

// ---------------------------------------------------------------------------
extern "C" void kernel_launch(void* const* d_in, const int* in_sizes, int n_in,
                              void* d_out, int out_size) {
    const float* fp = (const float*)d_in[0];
    const float* base_w1 = (const float*)d_in[1];
    const float* spline_w1 = (const float*)d_in[2];
    const float* scaler1 = (const float*)d_in[3];
    const float* base_w2 = (const float*)d_in[4];
    const float* spline_w2 = (const float*)d_in[5];
    const float* scaler2 = (const float*)d_in[6];
    float* out = (float*)d_out;

    uint32_t *w1t, *w2t;
    float* hp;
    cudaGetSymbolAddress((void**)&w1t, g_w1t);
    cudaGetSymbolAddress((void**)&w2t, g_w2t);
    cudaGetSymbolAddress((void**)&hp, g_h);

    cudaFuncSetAttribute(kan_mma_kernel,
                         cudaFuncAttributeMaxDynamicSharedMemorySize, SMEM_TOTAL);

    int chunks1 = NT1 * KT1 * 1024;
    int chunks2 = NT2 * KT2 * 1024;
    prep_kernel<<<(chunks1 + 255) / 256, 256>>>(w1t, base_w1, spline_w1, scaler1,
                                                KT1, F1, N1, chunks1);
    prep_kernel<<<(chunks2 + 255) / 256, 256>>>(w2t, base_w2, spline_w2, scaler2,
                                                KT2, F2, N2, chunks2);

    kan_mma_kernel<<<dim3(NT1, BATCH / 128), NTHREADS, SMEM_TOTAL>>>(
        fp, w1t, hp, F1, KT1, N1, N1, /*relu=*/1);
    kan_mma_kernel<<<dim3(NT2, BATCH / 128), NTHREADS, SMEM_TOTAL>>>(
        hp, w2t, out, F2, KT2, N2, N2, /*relu=*/0);
}

// round 13
// speedup vs baseline: 1.0020x; 1.0020x over previous
#include <cuda_runtime.h>
#include <cuda_bf16.h>
#include <cstdint>

// ---------------------------------------------------------------------------
// KAN 2-layer network on tcgen05 (kind::f16, bf16 inputs, fp32 accum) using a
// 3-term bf16 split for fp32-grade precision:
//   a*b ~= ah*bh + ah*bl + al*bh        (al*bl ~ 2^-18 dropped)
// f32x2 SIMT fallback for the non-arch-specific compute_103 pass.
//
// R11: 9-warp block. Warps 0-7 (256 thr) = A producers (2 features/thread,
// X prefetched ahead of the empty-wait); warp 8 = MMA issuer; warps 0-3 =
// TMEM epilogue. B tiles pre-split/pre-swizzled in gmem, fetched with one
// cp.async.bulk per tile onto the same barrier as the producer arrivals.
// ---------------------------------------------------------------------------

#if defined(__CUDA_ARCH__) && (defined(__CUDA_ARCH_FEAT_SM103_ALL) || \
                               defined(__CUDA_ARCH_FEAT_SM100_ALL) || \
                               defined(__CUDA_ARCH_FEAT_SM101_ALL))
#define KAN_TCGEN05 1
#else
#define KAN_TCGEN05 0
#endif

namespace {
constexpr int BATCH = 8192;
constexpr int F1 = 2513, N1 = 512;
constexpr int F2 = 512;
constexpr int N2 = 300;
constexpr int KT1 = 629;   // ceil(2513*8/32) k-tiles (32 expanded k each)
constexpr int KT2 = 128;   // 512*8/32
constexpr int NT1 = 4;
constexpr int NT2 = 3;
constexpr int NSTAGE = 3;
constexpr int TILE_BYTES = 16384;   // 128 rows x 128B
constexpr int TILE_U32 = 4096;
constexpr int NTHREADS = 288;       // 8 producer warps + 1 MMA warp

constexpr int OFF_TMEM = 0;
constexpr int OFF_BAR = 16;
constexpr int OFF_TILES = 1024;
constexpr int STAGE_BYTES = 32768;  // A(16KB) + B(16KB)
constexpr int SMEM_TOTAL = OFF_TILES + NSTAGE * STAGE_BYTES;  // 99328
}  // namespace

__device__ uint32_t g_w1t[(size_t)NT1 * KT1 * TILE_U32];
__device__ uint32_t g_w2t[(size_t)NT2 * KT2 * TILE_U32];
__device__ float g_h[(size_t)BATCH * 512];

typedef unsigned long long u64;

// --------------------- closed-form cubic B-spline expansion ----------------
// grid g[k] = (k-3)*0.4 - 1; inputs >= 0. t = floor(x*2.5 + 5.5); nonzero
// bases j in [t-3,t] ∩ [2,7].  o[0]=silu(x), o[1..6]=B_{2..7}(x), o[7]=0.
__device__ __forceinline__ void feats8(float x, float* o) {
    float s = fmaf(x, 2.5f, 5.5f);
    float tf = floorf(s);
    int t = (int)tf;
    float u = s - tf;
    float u2 = u * u, u3 = u2 * u;
    float p0 = u3 * (1.f / 6.f);
    float p1 = (fmaf(-3.f, u3, 3.f * u2) + 3.f * u + 1.f) * (1.f / 6.f);
    float p2 = (fmaf(3.f, u3, -6.f * u2) + 4.f) * (1.f / 6.f);
    float w = 1.f - u;
    float p3 = w * w * w * (1.f / 6.f);
    o[0] = x * __fdividef(1.f, 1.f + __expf(-x));
#pragma unroll
    for (int j = 2; j <= 7; j++) {
        int d = t - j;
        float v = 0.f;
        if (d == 0) v = p0;
        else if (d == 1) v = p1;
        else if (d == 2) v = p2;
        else if (d == 3) v = p3;
        o[j - 1] = v;
    }
    o[7] = 0.f;
}

__device__ __forceinline__ float bf_lo_f(uint32_t u) {
    return __uint_as_float(u << 16);
}
__device__ __forceinline__ float bf_hi_f(uint32_t u) {
    return __uint_as_float(u & 0xffff0000u);
}
__device__ __forceinline__ uint32_t pack_bf2(float a, float b) {
    __nv_bfloat162 p = __floats2bfloat162_rn(a, b);  // a->low, b->high
    return *reinterpret_cast<uint32_t*>(&p);
}

// --------------------------- weight prep -----------------------------------
// Tile T = ntile*KT + kt: 128 rows x 8 chunks of 16B, stored chunk =
// logical ^ (row&7).  Logical chunk j: j<4 -> hi bf16 of feature f=kt*4+j,
// slots s=0..7;  j>=4 -> lo residual of feature f=kt*4+(j-4).
// slot s: 0 -> base_w[n][f]; 1..6 -> spline_w[n][f][s+1]*scaler; 7 -> 0.
__global__ void prep_kernel(uint32_t* __restrict__ dst,
                            const float* __restrict__ base_w,
                            const float* __restrict__ spline_w,
                            const float* __restrict__ scaler, int KT, int F,
                            int Nsrc, int totalChunks) {
    int idx = blockIdx.x * blockDim.x + threadIdx.x;
    if (idx >= totalChunks) return;
    int cw = idx & 1023;
    int T = idx >> 10;
    int ntile = T / KT;
    int kt = T - ntile * KT;
    int r = cw >> 3;
    int js = cw & 7;
    int j = js ^ (r & 7);
    int c = j & 3;
    int isLo = j >> 2;
    int n = ntile * 128 + r;
    int f = kt * 4 + c;

    float wv[8];
#pragma unroll
    for (int s = 0; s < 8; s++) {
        float val = 0.f;
        if (n < Nsrc && f < F && s < 7) {
            size_t src = (size_t)n * F + f;
            if (s == 0) val = base_w[src];
            else val = spline_w[src * 8 + s + 1] * scaler[src];
        }
        wv[s] = val;
    }
    uint32_t out[4];
#pragma unroll
    for (int w = 0; w < 4; w++) {
        uint32_t hu = pack_bf2(wv[2 * w], wv[2 * w + 1]);
        if (!isLo) {
            out[w] = hu;
        } else {
            float r0 = wv[2 * w] - bf_lo_f(hu);
            float r1 = wv[2 * w + 1] - bf_hi_f(hu);
            out[w] = pack_bf2(r0, r1);
        }
    }
    *reinterpret_cast<uint4*>(dst + (size_t)T * TILE_U32 + cw * 4) =
        make_uint4(out[0], out[1], out[2], out[3]);
}

// ----------------------------- fused GEMM ----------------------------------
__global__ void __launch_bounds__(NTHREADS, 2) kan_mma_kernel(
    const float* __restrict__ X, const uint32_t* __restrict__ Wt,
    float* __restrict__ C, int F, int KT, int Nout, int Cstride, int doRelu) {
#if KAN_TCGEN05
    // ======================= tcgen05 bf16x3 path ============================
    extern __shared__ __align__(1024) char smem[];
    uint32_t sb;
    asm("{ .reg .u64 t; cvta.to.shared.u64 t, %1; cvt.u32.u64 %0, t; }"
        : "=r"(sb) : "l"(smem));
    const int tid = threadIdx.x;
    const int wid = tid >> 5;
    const int lane = tid & 31;
    const int m0 = blockIdx.y * 128;
    const int ntile = blockIdx.x;
    const int n0 = ntile * 128;
    const uint32_t bar = sb + OFF_BAR;
    // abfull[s]=bar+s*8 (257: 256 producers + expect_tx arrive)
    // empty[s]=bar+(NSTAGE+s)*8 (1: MMA commit)   done=bar+2*NSTAGE*8 (1)

#define MBAR_INIT(addr, cnt) \
    asm volatile("mbarrier.init.shared.b64 [%0], %1;" ::"r"(addr), "r"(cnt) : "memory")
#define MBAR_ARRIVE(addr) \
    asm volatile("mbarrier.arrive.shared.b64 _, [%0];" ::"r"(addr) : "memory")
#define MBAR_WAIT(addr, parity)                                                  \
    do {                                                                         \
        uint32_t _m = (addr), _p = (parity), _d;                                 \
        asm volatile(                                                            \
            "{\n\t.reg .pred p;\n\t"                                             \
            "mbarrier.try_wait.parity.acquire.cta.shared::cta.b64 p, [%1], %2;\n\t" \
            "selp.b32 %0, 1, 0, p;\n\t}"                                         \
            : "=r"(_d) : "r"(_m), "r"(_p) : "memory");                           \
        if (!_d) {                                                               \
            asm volatile(                                                        \
                "{\n\t.reg .pred P1;\n\t"                                        \
                "WL_%=:\n\t"                                                     \
                "mbarrier.try_wait.parity.acquire.cta.shared::cta.b64 P1, [%0], %1, 0x989680;\n\t" \
                "@P1 bra.uni WD_%=;\n\t"                                         \
                "bra.uni WL_%=;\n\t"                                             \
                "WD_%=:\n\t}" ::"r"(_m), "r"(_p) : "memory");                    \
        }                                                                        \
    } while (0)
#define STS128X(a, r0, r1, r2, r3) \
    asm volatile("st.shared.v4.b32 [%0], {%1,%2,%3,%4};" ::"r"(a), "r"(r0), "r"(r1), "r"(r2), "r"(r3) : "memory")

    if (wid == 8) {
        asm volatile(
            "tcgen05.alloc.cta_group::1.sync.aligned.shared::cta.b32 [%0], %1;"
            ::"r"(sb + OFF_TMEM), "r"(128) : "memory");
        asm volatile("tcgen05.relinquish_alloc_permit.cta_group::1.sync.aligned;");
    }
    if (tid == 0) {
#pragma unroll
        for (int s = 0; s < NSTAGE; s++) {
            MBAR_INIT(bar + s * 8, 257);                 // abfull
            MBAR_INIT(bar + (NSTAGE + s) * 8, 1);        // empty
        }
        MBAR_INIT(bar + 2 * NSTAGE * 8, 1);              // done
    }
    __syncthreads();

    if (tid < 256) {
        // -------- producers: 2 features/thread, X prefetch, B bulk-copy -----
        const int row = tid & 127;
        const int half = tid >> 7;             // feature pair within the 4
        const int r7 = row & 7;
        const float* Xr = X + (size_t)(m0 + row) * F + 2 * half;
        const uint32_t rowb_base = sb + OFF_TILES + row * 128;

        float xc0, xc1, xn0, xn1;
        {
            int f = 2 * half;
            xc0 = (f < F) ? __ldg(Xr) : 0.f;
            xc1 = (f + 1 < F) ? __ldg(Xr + 1) : 0.f;
        }
        int stage = 0, ph = 1;
        for (int t = 0; t < KT; t++) {
            // prefetch next tile's X before blocking on empty
            if (t + 1 < KT) {
                int f = (t + 1) * 4 + 2 * half;
                xn0 = (f < F) ? __ldg(Xr + (t + 1) * 4) : 0.f;
                xn1 = (f + 1 < F) ? __ldg(Xr + (t + 1) * 4 + 1) : 0.f;
            } else {
                xn0 = xn1 = 0.f;
            }
            MBAR_WAIT(bar + (NSTAGE + stage) * 8, ph);
            uint32_t As = sb + OFF_TILES + stage * STAGE_BYTES;
            if (tid == 0) {
                uint32_t abfull = bar + stage * 8;
                asm volatile(
                    "mbarrier.arrive.expect_tx.shared.b64 _, [%0], %1;"
                    ::"r"(abfull), "r"(TILE_BYTES) : "memory");
                const char* src = (const char*)Wt +
                                  (size_t)(ntile * KT + t) * TILE_BYTES;
                asm volatile(
                    "cp.async.bulk.shared::cluster.global.mbarrier::complete_tx::bytes "
                    "[%0], [%1], %2, [%3];"
                    ::"r"(As + TILE_BYTES), "l"(src), "r"(TILE_BYTES),
                      "r"(abfull) : "memory");
            }
            uint32_t rowb = rowb_base + stage * STAGE_BYTES;
#pragma unroll
            for (int q = 0; q < 2; q++) {
                float x = q ? xc1 : xc0;
                float o[8];
                feats8(x, o);
                uint32_t hi[4], lo[4];
#pragma unroll
                for (int w = 0; w < 4; w++) {
                    uint32_t hu = pack_bf2(o[2 * w], o[2 * w + 1]);
                    float r0 = o[2 * w] - bf_lo_f(hu);
                    float r1 = o[2 * w + 1] - bf_hi_f(hu);
                    hi[w] = hu;
                    lo[w] = pack_bf2(r0, r1);
                }
                int c = 2 * half + q;
                STS128X(rowb + ((c ^ r7) << 4), hi[0], hi[1], hi[2], hi[3]);
                STS128X(rowb + (((4 + c) ^ r7) << 4), lo[0], lo[1], lo[2], lo[3]);
            }
            asm volatile("fence.proxy.async.shared::cta;" ::: "memory");
            MBAR_ARRIVE(bar + stage * 8);
            xc0 = xn0;
            xc1 = xn1;
            if (++stage == NSTAGE) { stage = 0; ph ^= 1; }
        }
    } else {
        // ----------------------------- MMA warp (wid 8) ---------------------
        uint32_t tmem;
        asm volatile("ld.shared.b32 %0, [%1];" : "=r"(tmem) : "r"(sb + OFF_TMEM));
        const uint32_t idesc = (1u << 4) | (1u << 7) | (1u << 10) |
                               ((128u / 8u) << 17) | ((128u / 16u) << 24);
        uint32_t is_elected;
        asm volatile(
            "{\n\t.reg .pred p;\n\telect.sync _|p, 0xFFFFFFFF;\n\t"
            "selp.b32 %0, 1, 0, p;\n\t}" : "=r"(is_elected));
        int stage = 0, ph = 0;
        for (int t = 0; t < KT; t++) {
            MBAR_WAIT(bar + stage * 8, ph);  // abfull (A arrivals + B tx)
            if (is_elected) {
                uint32_t As = sb + OFF_TILES + stage * STAGE_BYTES;
                uint64_t base = (uint64_t(2) << 61) | (uint64_t(1) << 46) |
                                (uint64_t(64) << 32) | (uint64_t(1) << 16);
                uint64_t ad = base | ((uint64_t)(As >> 4) & 0x3FFF);
                uint64_t bd = base | ((uint64_t)((As + TILE_BYTES) >> 4) & 0x3FFF);
                // hi bytes [0,64): k0 at +0, k1 at +2; lo bytes [64,128): +4,+6
                const int aoff[6] = {0, 2, 0, 2, 4, 6};
                const int boff[6] = {0, 2, 4, 6, 0, 2};
#pragma unroll
                for (int s = 0; s < 6; s++) {
                    uint32_t en = !(t == 0 && s == 0);
                    asm volatile(
                        "{\n\t.reg .pred p;\n\tsetp.ne.u32 p, %5, 0;\n\t"
                        "tcgen05.mma.cta_group::1.kind::f16 [%0], %1, %2, %3, "
                        "{%4,%4,%4,%4}, p;\n\t}"
                        :: "r"(tmem), "l"(ad + aoff[s]), "l"(bd + boff[s]),
                           "r"(idesc), "r"(0u), "r"(en)
                        : "memory");
                }
                asm volatile(
                    "tcgen05.commit.cta_group::1.mbarrier::arrive::one.shared::cluster.b64 [%0];"
                    ::"r"(bar + (NSTAGE + stage) * 8) : "memory");
            }
            if (++stage == NSTAGE) { stage = 0; ph ^= 1; }
        }
        if (is_elected)
            asm volatile(
                "tcgen05.commit.cta_group::1.mbarrier::arrive::one.shared::cluster.b64 [%0];"
                ::"r"(bar + 2 * NSTAGE * 8) : "memory");
    }

    uint32_t tmem_all = 0;
    if (wid < 4 || wid == 8) {
        asm volatile("ld.shared.b32 %0, [%1];" : "=r"(tmem_all) : "r"(sb + OFF_TMEM));
    }
    if (wid < 4) {
        // ----------------------------- epilogue -----------------------------
        MBAR_WAIT(bar + 2 * NSTAGE * 8, 0);
        asm volatile("tcgen05.fence::after_thread_sync;" ::: "memory");
        const int wrow = (wid << 5) + lane;  // TMEM lane = M row
        const size_t m = (size_t)m0 + wrow;
        const bool fullTile = (n0 + 128 <= Nout);
#pragma unroll 1
        for (int ch = 0; ch < 4; ch++) {
            uint32_t r[32];
            asm volatile(
                "tcgen05.ld.sync.aligned.32x32b.x32.b32 "
                "{%0,%1,%2,%3,%4,%5,%6,%7,%8,%9,%10,%11,%12,%13,%14,%15,"
                "%16,%17,%18,%19,%20,%21,%22,%23,%24,%25,%26,%27,%28,%29,%30,%31}, [%32];"
                : "=r"(r[0]), "=r"(r[1]), "=r"(r[2]), "=r"(r[3]), "=r"(r[4]),
                  "=r"(r[5]), "=r"(r[6]), "=r"(r[7]), "=r"(r[8]), "=r"(r[9]),
                  "=r"(r[10]), "=r"(r[11]), "=r"(r[12]), "=r"(r[13]), "=r"(r[14]),
                  "=r"(r[15]), "=r"(r[16]), "=r"(r[17]), "=r"(r[18]), "=r"(r[19]),
                  "=r"(r[20]), "=r"(r[21]), "=r"(r[22]), "=r"(r[23]), "=r"(r[24]),
                  "=r"(r[25]), "=r"(r[26]), "=r"(r[27]), "=r"(r[28]), "=r"(r[29]),
                  "=r"(r[30]), "=r"(r[31])
                : "r"(tmem_all + ch * 32));
            asm volatile("tcgen05.wait::ld.sync.aligned;" ::: "memory");
            float vals[32];
#pragma unroll
            for (int c = 0; c < 32; c++) {
                float v = __uint_as_float(r[c]);
                vals[c] = doRelu ? fmaxf(v, 0.f) : v;
            }
            int nb = n0 + ch * 32;
            float* dst = C + m * Cstride + nb;
            if (fullTile) {
#pragma unroll
                for (int g = 0; g < 8; g++)
                    *(float4*)(dst + g * 4) = make_float4(
                        vals[g * 4], vals[g * 4 + 1], vals[g * 4 + 2], vals[g * 4 + 3]);
            } else {
#pragma unroll
                for (int c = 0; c < 32; c++)
                    if (nb + c < Nout) dst[c] = vals[c];
            }
        }
        asm volatile("tcgen05.fence::before_thread_sync;" ::: "memory");
    }

    __syncthreads();
    if (wid == 8)
        asm volatile("tcgen05.dealloc.cta_group::1.sync.aligned.b32 %0, %1;"
                     ::"r"(tmem_all), "r"(128));

#else
    // ====================== f32x2 SIMT fallback path ========================
    extern __shared__ __align__(1024) float fsm[];
    float* As = fsm;              // [32][132]
    float* Bs = fsm + 32 * 132;   // [32][128]
    const int tid = threadIdx.x;
    const int tx = tid & 15;
    const int ty = tid >> 4;
    const int m0 = blockIdx.y * 128;
    const int ntile = blockIdx.x;
    const int n0 = ntile * 128;

    u64 acc[8][4];
#pragma unroll
    for (int i = 0; i < 8; i++)
#pragma unroll
        for (int j = 0; j < 4; j++) acc[i][j] = 0ull;

    for (int t = 0; t < KT; t++) {
        __syncthreads();
        if (tid < 256) {
            // B tile: de-swizzle + hi/lo recombine into fp32 [k][n]
            for (int p = tid; p < 512; p += 256) {
                int r = p >> 2, c = p & 3;
                const uint4* tb =
                    (const uint4*)(Wt + (size_t)(ntile * KT + t) * TILE_U32 + r * 32);
                uint4 h4 = __ldg(&tb[c ^ (r & 7)]);
                uint4 l4 = __ldg(&tb[(4 + c) ^ (r & 7)]);
                uint32_t hw[4] = {h4.x, h4.y, h4.z, h4.w};
                uint32_t lw[4] = {l4.x, l4.y, l4.z, l4.w};
#pragma unroll
                for (int w = 0; w < 4; w++) {
                    Bs[(c * 8 + 2 * w) * 128 + r] = bf_lo_f(hw[w]) + bf_lo_f(lw[w]);
                    Bs[(c * 8 + 2 * w + 1) * 128 + r] = bf_hi_f(hw[w]) + bf_hi_f(lw[w]);
                }
            }
            // A tile: expand fp32
#pragma unroll
            for (int q = 0; q < 2; q++) {
                int p = tid + q * 256;
                int fi = p & 3;
                int mm = p >> 2;
                int f = t * 4 + fi;
                float x = (f < F) ? __ldg(&X[(size_t)(m0 + mm) * F + f]) : 0.f;
                float o[8];
                feats8(x, o);
#pragma unroll
                for (int s = 0; s < 8; s++) As[(fi * 8 + s) * 132 + mm] = o[s];
            }
        }
        __syncthreads();
        if (tid < 256) {
            const float* Ap = As + ty * 8;
            const float* Bp = Bs + tx * 8;
#pragma unroll
            for (int k = 0; k < 32; k++) {
                float4 a0 = *(const float4*)(Ap + k * 132);
                float4 a1 = *(const float4*)(Ap + k * 132 + 4);
                ulonglong2 b01 = *(const ulonglong2*)(Bp + k * 128);
                ulonglong2 b23 = *(const ulonglong2*)(Bp + k * 128 + 4);
                u64 bb[4] = {b01.x, b01.y, b23.x, b23.y};
                float av[8] = {a0.x, a0.y, a0.z, a0.w, a1.x, a1.y, a1.z, a1.w};
#pragma unroll
                for (int i = 0; i < 8; i++) {
                    u64 aa;
                    unsigned ui = __float_as_uint(av[i]);
                    asm("mov.b64 %0, {%1, %1};" : "=l"(aa) : "r"(ui));
#pragma unroll
                    for (int j = 0; j < 4; j++)
                        asm("fma.rn.f32x2 %0, %1, %2, %0;"
                            : "+l"(acc[i][j]) : "l"(aa), "l"(bb[j]));
                }
            }
        }
    }
    if (tid < 256) {
        const int colBase = n0 + tx * 8;
#pragma unroll
        for (int i = 0; i < 8; i++) {
            size_t row = m0 + ty * 8 + i;
            float o[8];
#pragma unroll
            for (int j = 0; j < 4; j++) {
                o[2 * j] = __uint_as_float((unsigned)(acc[i][j] & 0xffffffffull));
                o[2 * j + 1] = __uint_as_float((unsigned)(acc[i][j] >> 32));
            }
#pragma unroll
            for (int e = 0; e < 8; e++) {
                float v = doRelu ? fmaxf(o[e], 0.f) : o[e];
                if (colBase + e < Nout) C[row * Cstride + colBase + e] = v;
            }
        }
    }
#endif
}

// ---------------------------------------------------------------------------
extern "C" void kernel_launch(void* const* d_in, const int* in_sizes, int n_in,
                              void* d_out, int out_size) {
    const float* fp = (const float*)d_in[0];
    const float* base_w1 = (const float*)d_in[1];
    const float* spline_w1 = (const float*)d_in[2];
    const float* scaler1 = (const float*)d_in[3];
    const float* base_w2 = (const float*)d_in[4];
    const float* spline_w2 = (const float*)d_in[5];
    const float* scaler2 = (const float*)d_in[6];
    float* out = (float*)d_out;

    uint32_t *w1t, *w2t;
    float* hp;
    cudaGetSymbolAddress((void**)&w1t, g_w1t);
    cudaGetSymbolAddress((void**)&w2t, g_w2t);
    cudaGetSymbolAddress((void**)&hp, g_h);

    cudaFuncSetAttribute(kan_mma_kernel,
                         cudaFuncAttributeMaxDynamicSharedMemorySize, SMEM_TOTAL);

    int chunks1 = NT1 * KT1 * 1024;
    int chunks2 = NT2 * KT2 * 1024;
    prep_kernel<<<(chunks1 + 255) / 256, 256>>>(w1t, base_w1, spline_w1, scaler1,
                                                KT1, F1, N1, chunks1);
    prep_kernel<<<(chunks2 + 255) / 256, 256>>>(w2t, base_w2, spline_w2, scaler2,
                                                KT2, F2, N2, chunks2);

    kan_mma_kernel<<<dim3(NT1, BATCH / 128), NTHREADS, SMEM_TOTAL>>>(
        fp, w1t, hp, F1, KT1, N1, N1, /*relu=*/1);
    kan_mma_kernel<<<dim3(NT2, BATCH / 128), NTHREADS, SMEM_TOTAL>>>(
        hp, w2t, out, F2, KT2, N2, N2, /*relu=*/0);
}

// round 14
// speedup vs baseline: 1.0023x; 1.0003x over previous
#include <cuda_runtime.h>
#include <cuda_bf16.h>
#include <cstdint>

// ---------------------------------------------------------------------------
// KAN 2-layer network on tcgen05 (kind::f16, bf16 inputs, fp32 accum) using a
// 3-term bf16 split for fp32-grade precision:
//   a*b ~= ah*bh + ah*bl + al*bh        (al*bl ~ 2^-18 dropped)
// f32x2 SIMT fallback for the non-arch-specific compute_103 pass.
//
// R11: 9-warp block. Warps 0-7 (256 thr) = A producers (2 features/thread,
// X prefetched ahead of the empty-wait); warp 8 = MMA issuer; warps 0-3 =
// TMEM epilogue. B tiles pre-split/pre-swizzled in gmem, fetched with one
// cp.async.bulk per tile onto the same barrier as the producer arrivals.
// ---------------------------------------------------------------------------

#if defined(__CUDA_ARCH__) && (defined(__CUDA_ARCH_FEAT_SM103_ALL) || \
                               defined(__CUDA_ARCH_FEAT_SM100_ALL) || \
                               defined(__CUDA_ARCH_FEAT_SM101_ALL))
#define KAN_TCGEN05 1
#else
#define KAN_TCGEN05 0
#endif

namespace {
constexpr int BATCH = 8192;
constexpr int F1 = 2513, N1 = 512;
constexpr int F2 = 512;
constexpr int N2 = 300;
constexpr int KT1 = 629;   // ceil(2513*8/32) k-tiles (32 expanded k each)
constexpr int KT2 = 128;   // 512*8/32
constexpr int NT1 = 4;
constexpr int NT2 = 3;
constexpr int NSTAGE = 3;
constexpr int TILE_BYTES = 16384;   // 128 rows x 128B
constexpr int TILE_U32 = 4096;
constexpr int NTHREADS = 288;       // 8 producer warps + 1 MMA warp

constexpr int OFF_TMEM = 0;
constexpr int OFF_BAR = 16;
constexpr int OFF_TILES = 1024;
constexpr int STAGE_BYTES = 32768;  // A(16KB) + B(16KB)
constexpr int SMEM_TOTAL = OFF_TILES + NSTAGE * STAGE_BYTES;  // 99328
}  // namespace

__device__ uint32_t g_w1t[(size_t)NT1 * KT1 * TILE_U32];
__device__ uint32_t g_w2t[(size_t)NT2 * KT2 * TILE_U32];
__device__ float g_h[(size_t)BATCH * 512];

typedef unsigned long long u64;

// --------------------- closed-form cubic B-spline expansion ----------------
// grid g[k] = (k-3)*0.4 - 1; inputs >= 0. t = floor(x*2.5 + 5.5); nonzero
// bases j in [t-3,t] ∩ [2,7].  o[0]=silu(x), o[1..6]=B_{2..7}(x), o[7]=0.
__device__ __forceinline__ void feats8(float x, float* o) {
    float s = fmaf(x, 2.5f, 5.5f);
    float tf = floorf(s);
    int t = (int)tf;
    float u = s - tf;
    float u2 = u * u, u3 = u2 * u;
    float p0 = u3 * (1.f / 6.f);
    float p1 = (fmaf(-3.f, u3, 3.f * u2) + 3.f * u + 1.f) * (1.f / 6.f);
    float p2 = (fmaf(3.f, u3, -6.f * u2) + 4.f) * (1.f / 6.f);
    float w = 1.f - u;
    float p3 = w * w * w * (1.f / 6.f);
    o[0] = x * __fdividef(1.f, 1.f + __expf(-x));
#pragma unroll
    for (int j = 2; j <= 7; j++) {
        int d = t - j;
        float v = 0.f;
        if (d == 0) v = p0;
        else if (d == 1) v = p1;
        else if (d == 2) v = p2;
        else if (d == 3) v = p3;
        o[j - 1] = v;
    }
    o[7] = 0.f;
}

__device__ __forceinline__ float bf_lo_f(uint32_t u) {
    return __uint_as_float(u << 16);
}
__device__ __forceinline__ float bf_hi_f(uint32_t u) {
    return __uint_as_float(u & 0xffff0000u);
}
__device__ __forceinline__ uint32_t pack_bf2(float a, float b) {
    __nv_bfloat162 p = __floats2bfloat162_rn(a, b);  // a->low, b->high
    return *reinterpret_cast<uint32_t*>(&p);
}

// --------------------------- weight prep -----------------------------------
// Tile T = ntile*KT + kt: 128 rows x 8 chunks of 16B, stored chunk =
// logical ^ (row&7).  Logical chunk j: j<4 -> hi bf16 of feature f=kt*4+j,
// slots s=0..7;  j>=4 -> lo residual of feature f=kt*4+(j-4).
// slot s: 0 -> base_w[n][f]; 1..6 -> spline_w[n][f][s+1]*scaler; 7 -> 0.
__global__ void prep_kernel(uint32_t* __restrict__ dst,
                            const float* __restrict__ base_w,
                            const float* __restrict__ spline_w,
                            const float* __restrict__ scaler, int KT, int F,
                            int Nsrc, int totalChunks) {
    int idx = blockIdx.x * blockDim.x + threadIdx.x;
    if (idx >= totalChunks) return;
    int cw = idx & 1023;
    int T = idx >> 10;
    int ntile = T / KT;
    int kt = T - ntile * KT;
    int r = cw >> 3;
    int js = cw & 7;
    int j = js ^ (r & 7);
    int c = j & 3;
    int isLo = j >> 2;
    int n = ntile * 128 + r;
    int f = kt * 4 + c;

    float wv[8];
#pragma unroll
    for (int s = 0; s < 8; s++) {
        float val = 0.f;
        if (n < Nsrc && f < F && s < 7) {
            size_t src = (size_t)n * F + f;
            if (s == 0) val = base_w[src];
            else val = spline_w[src * 8 + s + 1] * scaler[src];
        }
        wv[s] = val;
    }
    uint32_t out[4];
#pragma unroll
    for (int w = 0; w < 4; w++) {
        uint32_t hu = pack_bf2(wv[2 * w], wv[2 * w + 1]);
        if (!isLo) {
            out[w] = hu;
        } else {
            float r0 = wv[2 * w] - bf_lo_f(hu);
            float r1 = wv[2 * w + 1] - bf_hi_f(hu);
            out[w] = pack_bf2(r0, r1);
        }
    }
    *reinterpret_cast<uint4*>(dst + (size_t)T * TILE_U32 + cw * 4) =
        make_uint4(out[0], out[1], out[2], out[3]);
}

// ----------------------------- fused GEMM ----------------------------------
__global__ void __launch_bounds__(NTHREADS, 2) kan_mma_kernel(
    const float* __restrict__ X, const uint32_t* __restrict__ Wt,
    float* __restrict__ C, int F, int KT, int Nout, int Cstride, int doRelu) {
#if KAN_TCGEN05
    // ======================= tcgen05 bf16x3 path ============================
    extern __shared__ __align__(1024) char smem[];
    uint32_t sb;
    asm("{ .reg .u64 t; cvta.to.shared.u64 t, %1; cvt.u32.u64 %0, t; }"
        : "=r"(sb) : "l"(smem));
    const int tid = threadIdx.x;
    const int wid = tid >> 5;
    const int lane = tid & 31;
    const int m0 = blockIdx.y * 128;
    const int ntile = blockIdx.x;
    const int n0 = ntile * 128;
    const uint32_t bar = sb + OFF_BAR;
    // abfull[s]=bar+s*8 (257: 256 producers + expect_tx arrive)
    // empty[s]=bar+(NSTAGE+s)*8 (1: MMA commit)   done=bar+2*NSTAGE*8 (1)

#define MBAR_INIT(addr, cnt) \
    asm volatile("mbarrier.init.shared.b64 [%0], %1;" ::"r"(addr), "r"(cnt) : "memory")
#define MBAR_ARRIVE(addr) \
    asm volatile("mbarrier.arrive.shared.b64 _, [%0];" ::"r"(addr) : "memory")
#define MBAR_WAIT(addr, parity)                                                  \
    do {                                                                         \
        uint32_t _m = (addr), _p = (parity), _d;                                 \
        asm volatile(                                                            \
            "{\n\t.reg .pred p;\n\t"                                             \
            "mbarrier.try_wait.parity.acquire.cta.shared::cta.b64 p, [%1], %2;\n\t" \
            "selp.b32 %0, 1, 0, p;\n\t}"                                         \
            : "=r"(_d) : "r"(_m), "r"(_p) : "memory");                           \
        if (!_d) {                                                               \
            asm volatile(                                                        \
                "{\n\t.reg .pred P1;\n\t"                                        \
                "WL_%=:\n\t"                                                     \
                "mbarrier.try_wait.parity.acquire.cta.shared::cta.b64 P1, [%0], %1, 0x989680;\n\t" \
                "@P1 bra.uni WD_%=;\n\t"                                         \
                "bra.uni WL_%=;\n\t"                                             \
                "WD_%=:\n\t}" ::"r"(_m), "r"(_p) : "memory");                    \
        }                                                                        \
    } while (0)
#define STS128X(a, r0, r1, r2, r3) \
    asm volatile("st.shared.v4.b32 [%0], {%1,%2,%3,%4};" ::"r"(a), "r"(r0), "r"(r1), "r"(r2), "r"(r3) : "memory")

    if (wid == 8) {
        asm volatile(
            "tcgen05.alloc.cta_group::1.sync.aligned.shared::cta.b32 [%0], %1;"
            ::"r"(sb + OFF_TMEM), "r"(128) : "memory");
        asm volatile("tcgen05.relinquish_alloc_permit.cta_group::1.sync.aligned;");
    }
    if (tid == 0) {
#pragma unroll
        for (int s = 0; s < NSTAGE; s++) {
            MBAR_INIT(bar + s * 8, 257);                 // abfull
            MBAR_INIT(bar + (NSTAGE + s) * 8, 1);        // empty
        }
        MBAR_INIT(bar + 2 * NSTAGE * 8, 1);              // done
    }
    __syncthreads();

    if (tid < 256) {
        // -------- producers: 2 features/thread, X prefetch, B bulk-copy -----
        const int row = tid & 127;
        const int half = tid >> 7;             // feature pair within the 4
        const int r7 = row & 7;
        const float* Xr = X + (size_t)(m0 + row) * F + 2 * half;
        const uint32_t rowb_base = sb + OFF_TILES + row * 128;

        float xc0, xc1, xn0, xn1;
        {
            int f = 2 * half;
            xc0 = (f < F) ? __ldg(Xr) : 0.f;
            xc1 = (f + 1 < F) ? __ldg(Xr + 1) : 0.f;
        }
        int stage = 0, ph = 1;
        for (int t = 0; t < KT; t++) {
            // prefetch next tile's X before blocking on empty
            if (t + 1 < KT) {
                int f = (t + 1) * 4 + 2 * half;
                xn0 = (f < F) ? __ldg(Xr + (t + 1) * 4) : 0.f;
                xn1 = (f + 1 < F) ? __ldg(Xr + (t + 1) * 4 + 1) : 0.f;
            } else {
                xn0 = xn1 = 0.f;
            }
            MBAR_WAIT(bar + (NSTAGE + stage) * 8, ph);
            uint32_t As = sb + OFF_TILES + stage * STAGE_BYTES;
            if (tid == 0) {
                uint32_t abfull = bar + stage * 8;
                asm volatile(
                    "mbarrier.arrive.expect_tx.shared.b64 _, [%0], %1;"
                    ::"r"(abfull), "r"(TILE_BYTES) : "memory");
                const char* src = (const char*)Wt +
                                  (size_t)(ntile * KT + t) * TILE_BYTES;
                asm volatile(
                    "cp.async.bulk.shared::cluster.global.mbarrier::complete_tx::bytes "
                    "[%0], [%1], %2, [%3];"
                    ::"r"(As + TILE_BYTES), "l"(src), "r"(TILE_BYTES),
                      "r"(abfull) : "memory");
            }
            uint32_t rowb = rowb_base + stage * STAGE_BYTES;
#pragma unroll
            for (int q = 0; q < 2; q++) {
                float x = q ? xc1 : xc0;
                float o[8];
                feats8(x, o);
                uint32_t hi[4], lo[4];
#pragma unroll
                for (int w = 0; w < 4; w++) {
                    uint32_t hu = pack_bf2(o[2 * w], o[2 * w + 1]);
                    float r0 = o[2 * w] - bf_lo_f(hu);
                    float r1 = o[2 * w + 1] - bf_hi_f(hu);
                    hi[w] = hu;
                    lo[w] = pack_bf2(r0, r1);
                }
                int c = 2 * half + q;
                STS128X(rowb + ((c ^ r7) << 4), hi[0], hi[1], hi[2], hi[3]);
                STS128X(rowb + (((4 + c) ^ r7) << 4), lo[0], lo[1], lo[2], lo[3]);
            }
            asm volatile("fence.proxy.async.shared::cta;" ::: "memory");
            MBAR_ARRIVE(bar + stage * 8);
            xc0 = xn0;
            xc1 = xn1;
            if (++stage == NSTAGE) { stage = 0; ph ^= 1; }
        }
    } else {
        // ----------------------------- MMA warp (wid 8) ---------------------
        uint32_t tmem;
        asm volatile("ld.shared.b32 %0, [%1];" : "=r"(tmem) : "r"(sb + OFF_TMEM));
        const uint32_t idesc = (1u << 4) | (1u << 7) | (1u << 10) |
                               ((128u / 8u) << 17) | ((128u / 16u) << 24);
        uint32_t is_elected;
        asm volatile(
            "{\n\t.reg .pred p;\n\telect.sync _|p, 0xFFFFFFFF;\n\t"
            "selp.b32 %0, 1, 0, p;\n\t}" : "=r"(is_elected));
        int stage = 0, ph = 0;
        for (int t = 0; t < KT; t++) {
            MBAR_WAIT(bar + stage * 8, ph);  // abfull (A arrivals + B tx)
            if (is_elected) {
                uint32_t As = sb + OFF_TILES + stage * STAGE_BYTES;
                uint64_t base = (uint64_t(2) << 61) | (uint64_t(1) << 46) |
                                (uint64_t(64) << 32) | (uint64_t(1) << 16);
                uint64_t ad = base | ((uint64_t)(As >> 4) & 0x3FFF);
                uint64_t bd = base | ((uint64_t)((As + TILE_BYTES) >> 4) & 0x3FFF);
                // hi bytes [0,64): k0 at +0, k1 at +2; lo bytes [64,128): +4,+6
                const int aoff[6] = {0, 2, 0, 2, 4, 6};
                const int boff[6] = {0, 2, 4, 6, 0, 2};
#pragma unroll
                for (int s = 0; s < 6; s++) {
                    uint32_t en = !(t == 0 && s == 0);
                    asm volatile(
                        "{\n\t.reg .pred p;\n\tsetp.ne.u32 p, %5, 0;\n\t"
                        "tcgen05.mma.cta_group::1.kind::f16 [%0], %1, %2, %3, "
                        "{%4,%4,%4,%4}, p;\n\t}"
                        :: "r"(tmem), "l"(ad + aoff[s]), "l"(bd + boff[s]),
                           "r"(idesc), "r"(0u), "r"(en)
                        : "memory");
                }
                asm volatile(
                    "tcgen05.commit.cta_group::1.mbarrier::arrive::one.shared::cluster.b64 [%0];"
                    ::"r"(bar + (NSTAGE + stage) * 8) : "memory");
            }
            if (++stage == NSTAGE) { stage = 0; ph ^= 1; }
        }
        if (is_elected)
            asm volatile(
                "tcgen05.commit.cta_group::1.mbarrier::arrive::one.shared::cluster.b64 [%0];"
                ::"r"(bar + 2 * NSTAGE * 8) : "memory");
    }

    uint32_t tmem_all = 0;
    if (wid < 4 || wid == 8) {
        asm volatile("ld.shared.b32 %0, [%1];" : "=r"(tmem_all) : "r"(sb + OFF_TMEM));
    }
    if (wid < 4) {
        // ----------------------------- epilogue -----------------------------
        MBAR_WAIT(bar + 2 * NSTAGE * 8, 0);
        asm volatile("tcgen05.fence::after_thread_sync;" ::: "memory");
        const int wrow = (wid << 5) + lane;  // TMEM lane = M row
        const size_t m = (size_t)m0 + wrow;
        const bool fullTile = (n0 + 128 <= Nout);
#pragma unroll 1
        for (int ch = 0; ch < 4; ch++) {
            uint32_t r[32];
            asm volatile(
                "tcgen05.ld.sync.aligned.32x32b.x32.b32 "
                "{%0,%1,%2,%3,%4,%5,%6,%7,%8,%9,%10,%11,%12,%13,%14,%15,"
                "%16,%17,%18,%19,%20,%21,%22,%23,%24,%25,%26,%27,%28,%29,%30,%31}, [%32];"
                : "=r"(r[0]), "=r"(r[1]), "=r"(r[2]), "=r"(r[3]), "=r"(r[4]),
                  "=r"(r[5]), "=r"(r[6]), "=r"(r[7]), "=r"(r[8]), "=r"(r[9]),
                  "=r"(r[10]), "=r"(r[11]), "=r"(r[12]), "=r"(r[13]), "=r"(r[14]),
                  "=r"(r[15]), "=r"(r[16]), "=r"(r[17]), "=r"(r[18]), "=r"(r[19]),
                  "=r"(r[20]), "=r"(r[21]), "=r"(r[22]), "=r"(r[23]), "=r"(r[24]),
                  "=r"(r[25]), "=r"(r[26]), "=r"(r[27]), "=r"(r[28]), "=r"(r[29]),
                  "=r"(r[30]), "=r"(r[31])
                : "r"(tmem_all + ch * 32));
            asm volatile("tcgen05.wait::ld.sync.aligned;" ::: "memory");
            float vals[32];
#pragma unroll
            for (int c = 0; c < 32; c++) {
                float v = __uint_as_float(r[c]);
                vals[c] = doRelu ? fmaxf(v, 0.f) : v;
            }
            int nb = n0 + ch * 32;
            float* dst = C + m * Cstride + nb;
            if (fullTile) {
#pragma unroll
                for (int g = 0; g < 8; g++)
                    *(float4*)(dst + g * 4) = make_float4(
                        vals[g * 4], vals[g * 4 + 1], vals[g * 4 + 2], vals[g * 4 + 3]);
            } else {
#pragma unroll
                for (int c = 0; c < 32; c++)
                    if (nb + c < Nout) dst[c] = vals[c];
            }
        }
        asm volatile("tcgen05.fence::before_thread_sync;" ::: "memory");
    }

    __syncthreads();
    if (wid == 8)
        asm volatile("tcgen05.dealloc.cta_group::1.sync.aligned.b32 %0, %1;"
                     ::"r"(tmem_all), "r"(128));

#else
    // ====================== f32x2 SIMT fallback path ========================
    extern __shared__ __align__(1024) float fsm[];
    float* As = fsm;              // [32][132]
    float* Bs = fsm + 32 * 132;   // [32][128]
    const int tid = threadIdx.x;
    const int tx = tid & 15;
    const int ty = tid >> 4;
    const int m0 = blockIdx.y * 128;
    const int ntile = blockIdx.x;
    const int n0 = ntile * 128;

    u64 acc[8][4];
#pragma unroll
    for (int i = 0; i < 8; i++)
#pragma unroll
        for (int j = 0; j < 4; j++) acc[i][j] = 0ull;

    for (int t = 0; t < KT; t++) {
        __syncthreads();
        if (tid < 256) {
            // B tile: de-swizzle + hi/lo recombine into fp32 [k][n]
            for (int p = tid; p < 512; p += 256) {
                int r = p >> 2, c = p & 3;
                const uint4* tb =
                    (const uint4*)(Wt + (size_t)(ntile * KT + t) * TILE_U32 + r * 32);
                uint4 h4 = __ldg(&tb[c ^ (r & 7)]);
                uint4 l4 = __ldg(&tb[(4 + c) ^ (r & 7)]);
                uint32_t hw[4] = {h4.x, h4.y, h4.z, h4.w};
                uint32_t lw[4] = {l4.x, l4.y, l4.z, l4.w};
#pragma unroll
                for (int w = 0; w < 4; w++) {
                    Bs[(c * 8 + 2 * w) * 128 + r] = bf_lo_f(hw[w]) + bf_lo_f(lw[w]);
                    Bs[(c * 8 + 2 * w + 1) * 128 + r] = bf_hi_f(hw[w]) + bf_hi_f(lw[w]);
                }
            }
            // A tile: expand fp32
#pragma unroll
            for (int q = 0; q < 2; q++) {
                int p = tid + q * 256;
                int fi = p & 3;
                int mm = p >> 2;
                int f = t * 4 + fi;
                float x = (f < F) ? __ldg(&X[(size_t)(m0 + mm) * F + f]) : 0.f;
                float o[8];
                feats8(x, o);
#pragma unroll
                for (int s = 0; s < 8; s++) As[(fi * 8 + s) * 132 + mm] = o[s];
            }
        }
        __syncthreads();
        if (tid < 256) {
            const float* Ap = As + ty * 8;
            const float* Bp = Bs + tx * 8;
#pragma unroll
            for (int k = 0; k < 32; k++) {
                float4 a0 = *(const float4*)(Ap + k * 132);
                float4 a1 = *(const float4*)(Ap + k * 132 + 4);
                ulonglong2 b01 = *(const ulonglong2*)(Bp + k * 128);
                ulonglong2 b23 = *(const ulonglong2*)(Bp + k * 128 + 4);
                u64 bb[4] = {b01.x, b01.y, b23.x, b23.y};
                float av[8] = {a0.x, a0.y, a0.z, a0.w, a1.x, a1.y, a1.z, a1.w};
#pragma unroll
                for (int i = 0; i < 8; i++) {
                    u64 aa;
                    unsigned ui = __float_as_uint(av[i]);
                    asm("mov.b64 %0, {%1, %1};" : "=l"(aa) : "r"(ui));
#pragma unroll
                    for (int j = 0; j < 4; j++)
                        asm("fma.rn.f32x2 %0, %1, %2, %0;"
                            : "+l"(acc[i][j]) : "l"(aa), "l"(bb[j]));
                }
            }
        }
    }
    if (tid < 256) {
        const int colBase = n0 + tx * 8;
#pragma unroll
        for (int i = 0; i < 8; i++) {
            size_t row = m0 + ty * 8 + i;
            float o[8];
#pragma unroll
            for (int j = 0; j < 4; j++) {
                o[2 * j] = __uint_as_float((unsigned)(acc[i][j] & 0xffffffffull));
                o[2 * j + 1] = __uint_as_float((unsigned)(acc[i][j] >> 32));
            }
#pragma unroll
            for (int e = 0; e < 8; e++) {
                float v = doRelu ? fmaxf(o[e], 0.f) : o[e];
                if (colBase + e < Nout) C[row * Cstride + colBase + e] = v;
            }
        }
    }
#endif
}

// ---------------------------------------------------------------------------
extern "C" void kernel_launch(void* const* d_in, const int* in_sizes, int n_in,
                              void* d_out, int out_size) {
    const float* fp = (const float*)d_in[0];
    const float* base_w1 = (const float*)d_in[1];
    const float* spline_w1 = (const float*)d_in[2];
    const float* scaler1 = (const float*)d_in[3];
    const float* base_w2 = (const float*)d_in[4];
    const float* spline_w2 = (const float*)d_in[5];
    const float* scaler2 = (const float*)d_in[6];
    float* out = (float*)d_out;

    uint32_t *w1t, *w2t;
    float* hp;
    cudaGetSymbolAddress((void**)&w1t, g_w1t);
    cudaGetSymbolAddress((void**)&w2t, g_w2t);
    cudaGetSymbolAddress((void**)&hp, g_h);

    cudaFuncSetAttribute(kan_mma_kernel,
                         cudaFuncAttributeMaxDynamicSharedMemorySize, SMEM_TOTAL);

    int chunks1 = NT1 * KT1 * 1024;
    int chunks2 = NT2 * KT2 * 1024;
    prep_kernel<<<(chunks1 + 255) / 256, 256>>>(w1t, base_w1, spline_w1, scaler1,
                                                KT1, F1, N1, chunks1);
    prep_kernel<<<(chunks2 + 255) / 256, 256>>>(w2t, base_w2, spline_w2, scaler2,
                                                KT2, F2, N2, chunks2);

    kan_mma_kernel<<<dim3(NT1, BATCH / 128), NTHREADS, SMEM_TOTAL>>>(
        fp, w1t, hp, F1, KT1, N1, N1, /*relu=*/1);
    kan_mma_kernel<<<dim3(NT2, BATCH / 128), NTHREADS, SMEM_TOTAL>>>(
        hp, w2t, out, F2, KT2, N2, N2, /*relu=*/0);
}